// round 9
// baseline (speedup 1.0000x reference)
#include <cuda_runtime.h>
#include <cuda_bf16.h>
#include <cstdint>

#define KBLK   8
#define IDIM   96
#define ODIM   96
#define XYTOT  65160
#define XYH    (XYTOT/2)
#define XYT    32
#define NTHR   320
#define NCON   256
#define NTILES 2037            // ceil(65160/32)
#define NCHUNK 18

#define PITCH      224                   // 56 words; 56%32==24 -> conflict-free
#define A_TILE     (XYT * PITCH)         // 7168
#define ABUF       (6 * A_TILE)          // 43008
#define W_TILE     (ODIM * PITCH)        // 21504
#define SM_A       1024
#define SM_W       (SM_A + 2 * ABUF)     // 87040
#define SMEM_TOTAL (SM_W + 6 * W_TILE)   // 216064

static __device__ __forceinline__ void split2(float a, float b, uint32_t& hi, uint32_t& lo) {
    uint32_t ua = __float_as_uint(a), ub = __float_as_uint(b);
    asm("prmt.b32 %0, %1, %2, 0x7632;" : "=r"(hi) : "r"(ua), "r"(ub));
    float ra = a - __uint_as_float(ua & 0xFFFF0000u);
    float rb = b - __uint_as_float(ub & 0xFFFF0000u);
    asm("cvt.rn.bf16x2.f32 %0, %1, %2;" : "=r"(lo) : "f"(rb), "f"(ra));
}
static __device__ __forceinline__ int kword(int j) {
    return ((j >> 3) << 3) + ((j & 3) << 1) + ((j >> 2) & 1);
}
static __device__ __forceinline__ uint32_t smem_u32(const void* p) {
    uint32_t a;
    asm("{ .reg .u64 t; cvta.to.shared.u64 t, %1; cvt.u32.u64 %0, t; }" : "=r"(a) : "l"(p));
    return a;
}
static __device__ __forceinline__ void mbar_wait(uint32_t addr, int parity) {
    asm volatile(
        "{ .reg .pred P;\n\t"
        "WL%=: mbarrier.try_wait.parity.acquire.cta.shared::cta.b64 P, [%0], %1, 0x989680;\n\t"
        "@P bra WD%=;\n\t"
        "bra WL%=;\n\t"
        "WD%=: }"
        :: "r"(addr), "r"((uint32_t)parity) : "memory");
}
static __device__ __forceinline__ void mbar_arrive(uint32_t addr) {
    asm volatile("mbarrier.arrive.shared.b64 _, [%0];" :: "r"(addr) : "memory");
}

#define MMA(c, a, b)                                                            \
    asm volatile("mma.sync.aligned.m16n8k16.row.col.f32.bf16.bf16.f32 "         \
        "{%0,%1,%2,%3},{%4,%5,%6,%7},{%8,%9},{%0,%1,%2,%3};"                    \
        : "+f"((c)[0]), "+f"((c)[1]), "+f"((c)[2]), "+f"((c)[3])                \
        : "r"((a)[0]), "r"((a)[1]), "r"((a)[2]), "r"((a)[3]),                   \
          "r"((b).x), "r"((b).y))

// unit u (0..191): p = u/12 (xy-pair 0..15), h = u%12 -> b = h>>1 (16-i block), f = h&1
static __device__ __forceinline__ void prod_load(float4* v, const float4* s4, int u, int xy0) {
    const int p = u / 12, h = u % 12, b = h >> 1, f = h & 1;
    const int i0 = b * 16 + f * 4;
    const bool ok = (xy0 + 2 * p) < XYTOT;
    const size_t g4 = (size_t)(xy0 >> 1) + p;
    #pragma unroll
    for (int q = 0; q < 4; ++q) {
        v[q]     = ok ? __ldg(&s4[(size_t)(i0 + q)     * XYH + g4]) : make_float4(0.f,0.f,0.f,0.f);
        v[4 + q] = ok ? __ldg(&s4[(size_t)(i0 + 8 + q) * XYH + g4]) : make_float4(0.f,0.f,0.f,0.f);
    }
}

// store 8 elems of 3 variants (H tiles 0..2, L tiles 3..5) as one row-chunk each
static __device__ __forceinline__ void store6(unsigned char* sm, uint32_t off,
                                              const float* e0, const float* e1, const float* e2) {
    uint4 H, L;
    split2(e0[0],e0[1],H.x,L.x); split2(e0[4],e0[5],H.y,L.y);
    split2(e0[2],e0[3],H.z,L.z); split2(e0[6],e0[7],H.w,L.w);
    *(uint4*)(sm + off + 0*A_TILE) = H;  *(uint4*)(sm + off + 3*A_TILE) = L;
    split2(e1[0],e1[1],H.x,L.x); split2(e1[4],e1[5],H.y,L.y);
    split2(e1[2],e1[3],H.z,L.z); split2(e1[6],e1[7],H.w,L.w);
    *(uint4*)(sm + off + 1*A_TILE) = H;  *(uint4*)(sm + off + 4*A_TILE) = L;
    split2(e2[0],e2[1],H.x,L.x); split2(e2[4],e2[5],H.y,L.y);
    split2(e2[2],e2[3],H.z,L.z); split2(e2[6],e2[7],H.w,L.w);
    *(uint4*)(sm + off + 2*A_TILE) = H;  *(uint4*)(sm + off + 5*A_TILE) = L;
}

static __device__ __forceinline__ void prod_store(unsigned char* sm, const float4* v,
                                                  int u, uint32_t abase) {
    const int p = u / 12, h = u % 12, b = h >> 1, f = h & 1;
    uint32_t off = abase + (uint32_t)(2 * p) * PITCH + (uint32_t)(b * 32 + f * 16);
    float e0[8], e1[8], e2[8];
    #pragma unroll
    for (int q = 0; q < 8; ++q) {          // xy = 2p : (.x=re, .y=im)
        e0[q] = v[q].x;                    // Ar
        e1[q] = v[q].x + v[q].y;           // Ar+Ai
        e2[q] = v[q].y - v[q].x;           // Ai-Ar
    }
    store6(sm, off, e0, e1, e2);
    #pragma unroll
    for (int q = 0; q < 8; ++q) {          // xy = 2p+1 : (.z=re, .w=im)
        e0[q] = v[q].z;
        e1[q] = v[q].z + v[q].w;
        e2[q] = v[q].w - v[q].z;
    }
    store6(sm, off + PITCH, e0, e1, e2);
}

__global__ __launch_bounds__(NTHR, 1)
void cmul_k3(const float2* __restrict__ inp, const float2* __restrict__ wgt,
             const float2* __restrict__ bias, float2* __restrict__ out)
{
    extern __shared__ unsigned char sm[];
    const uint32_t smb = smem_u32(sm);
    const int tid = threadIdx.x, lane = tid & 31, wid = tid >> 5;
    const int kk = blockIdx.y, chunk = blockIdx.x;

    const int basecnt = NTILES / NCHUNK;            // 113
    const int rem     = NTILES - basecnt * NCHUNK;  // 3
    const int cnt     = basecnt + (chunk < rem ? 1 : 0);
    const int t0      = chunk * basecnt + (chunk < rem ? chunk : rem);

    if (tid == 0) {
        asm volatile("mbarrier.init.shared.b64 [%0], %1;" :: "r"(smb + 0),  "r"(64u)  : "memory");
        asm volatile("mbarrier.init.shared.b64 [%0], %1;" :: "r"(smb + 8),  "r"(64u)  : "memory");
        asm volatile("mbarrier.init.shared.b64 [%0], %1;" :: "r"(smb + 16), "r"(256u) : "memory");
        asm volatile("mbarrier.init.shared.b64 [%0], %1;" :: "r"(smb + 24), "r"(256u) : "memory");
    }

    // ---- stage W variants once: tiles [WsH, WiH, WrH, WsL, WiL, WrL] ----
    for (int u = tid; u < 96 * 48; u += NTHR) {
        const int o = u / 48, j = u % 48;
        const float2* src = wgt + (size_t)kk * IDIM * ODIM + o;
        float2 wa = src[(size_t)(2 * j)     * ODIM];   // (wr, wi) at i=2j
        float2 wb = src[(size_t)(2 * j + 1) * ODIM];
        const uint32_t off = (uint32_t)(o * PITCH + kword(j) * 4);
        uint32_t h, l;
        split2(wa.x + wa.y, wb.x + wb.y, h, l);        // Ws = Wr+Wi
        *(uint32_t*)(sm + SM_W + 0*W_TILE + off) = h;
        *(uint32_t*)(sm + SM_W + 3*W_TILE + off) = l;
        split2(wa.y, wb.y, h, l);                      // Wi
        *(uint32_t*)(sm + SM_W + 1*W_TILE + off) = h;
        *(uint32_t*)(sm + SM_W + 4*W_TILE + off) = l;
        split2(wa.x, wb.x, h, l);                      // Wr
        *(uint32_t*)(sm + SM_W + 2*W_TILE + off) = h;
        *(uint32_t*)(sm + SM_W + 5*W_TILE + off) = l;
    }
    __syncthreads();

    if (tid >= NCON) {
        // ================= PRODUCER (warps 8,9; 64 threads) =================
        const int ptid = tid - NCON;
        const float4* s4 = (const float4*)(inp + (size_t)kk * IDIM * XYTOT);
        int phe0 = 1, phe1 = 1;
        float4 v0[8], v1[8], v2[8];
        #pragma unroll 1
        for (int t = 0; t < cnt; ++t) {
            const int buf = t & 1;
            const int xy0 = (t0 + t) * XYT;
            const uint32_t abase = SM_A + buf * ABUF;
            prod_load(v0, s4, ptid,       xy0);
            prod_load(v1, s4, ptid + 64,  xy0);
            prod_load(v2, s4, ptid + 128, xy0);
            if (buf == 0) { mbar_wait(smb + 16, phe0); phe0 ^= 1; }
            else          { mbar_wait(smb + 24, phe1); phe1 ^= 1; }
            prod_store(sm, v0, ptid,       abase);
            prod_store(sm, v1, ptid + 64,  abase);
            prod_store(sm, v2, ptid + 128, abase);
            mbar_arrive(smb + buf * 8);  // full[buf]
        }
    } else {
        // ================= CONSUMER (warps 0-7; 256 threads) =================
        const int g = lane >> 2, tig = lane & 3;
        const int warpM = (wid & 1) * 16;      // xy rows within tile
        const int warpN = (wid >> 1) * 24;     // o columns

        float2 bv0[3], bv1[3];
        #pragma unroll
        for (int nt = 0; nt < 3; ++nt) {
            const int o0 = warpN + nt * 8 + 2 * tig;
            bv0[nt] = bias[kk * ODIM + o0];
            bv1[nt] = bias[kk * ODIM + o0 + 1];
        }
        float2* outk = out + (size_t)kk * ODIM * XYTOT;

        const uint32_t wOff = (uint32_t)(warpN + g) * PITCH;
        int phf0 = 0, phf1 = 0;
        #pragma unroll 1
        for (int t = 0; t < cnt; ++t) {
            const int buf = t & 1;
            if (buf == 0) { mbar_wait(smb + 0, phf0); phf0 ^= 1; }
            else          { mbar_wait(smb + 8, phf1); phf1 ^= 1; }

            float acc[3][3][4];               // [m1,m2,m3][nt][quad]
            #pragma unroll
            for (int p = 0; p < 3; ++p)
                #pragma unroll
                for (int nt = 0; nt < 3; ++nt)
                    #pragma unroll
                    for (int q = 0; q < 4; ++q) acc[p][nt][q] = 0.f;

            const uint32_t aBase = SM_A + buf * ABUF + (uint32_t)((warpM + g) * PITCH);

            #pragma unroll 1
            for (int ks = 0; ks < 6; ++ks) {
                const uint32_t koff = (uint32_t)(ks * 32 + tig * 8);
                uint32_t Af[6][4];
                #pragma unroll
                for (int at = 0; at < 6; ++at) {
                    const uint32_t ad = aBase + at * A_TILE + koff;
                    uint2 lo = *(const uint2*)(sm + ad);
                    uint2 hi = *(const uint2*)(sm + ad + 8 * PITCH);
                    Af[at][0] = lo.x; Af[at][1] = hi.x; Af[at][2] = lo.y; Af[at][3] = hi.y;
                }
                uint2 Bf[6][3];
                #pragma unroll
                for (int wt = 0; wt < 6; ++wt)
                    #pragma unroll
                    for (int nt = 0; nt < 3; ++nt)
                        Bf[wt][nt] = *(const uint2*)(sm + SM_W + wt * W_TILE +
                                      wOff + (uint32_t)(nt * 8 * PITCH) + koff);
                // 9 passes: s=0 HH, s=1 LH (A lo tiles), s=2 HL (W lo tiles)
                #pragma unroll
                for (int s = 0; s < 3; ++s)
                    #pragma unroll
                    for (int p = 0; p < 3; ++p) {
                        const int at = (s == 1) ? 3 + p : p;
                        const int wt = (s == 2) ? 3 + p : p;
                        #pragma unroll
                        for (int nt = 0; nt < 3; ++nt)
                            MMA(acc[p][nt], Af[at], Bf[wt][nt]);
                    }
            }

            mbar_arrive(smb + 16 + buf * 8);  // empty[buf] (acc in regs)

            // epilogue: re = m1 - m2 + br ; im = m1 + m3 + bi
            const int xyb = (t0 + t) * XYT + warpM;
            const int xyA = xyb + g, xyB = xyA + 8;
            const bool full = ((t0 + t) * XYT + XYT) <= XYTOT;
            #pragma unroll
            for (int nt = 0; nt < 3; ++nt) {
                const int o0 = warpN + nt * 8 + 2 * tig;
                float2 rA0 = make_float2(acc[0][nt][0] - acc[1][nt][0] + bv0[nt].x,
                                         acc[0][nt][0] + acc[2][nt][0] + bv0[nt].y);
                float2 rA1 = make_float2(acc[0][nt][1] - acc[1][nt][1] + bv1[nt].x,
                                         acc[0][nt][1] + acc[2][nt][1] + bv1[nt].y);
                float2 rB0 = make_float2(acc[0][nt][2] - acc[1][nt][2] + bv0[nt].x,
                                         acc[0][nt][2] + acc[2][nt][2] + bv0[nt].y);
                float2 rB1 = make_float2(acc[0][nt][3] - acc[1][nt][3] + bv1[nt].x,
                                         acc[0][nt][3] + acc[2][nt][3] + bv1[nt].y);
                if (full || xyA < XYTOT) {
                    outk[(size_t)o0       * XYTOT + xyA] = rA0;
                    outk[(size_t)(o0 + 1) * XYTOT + xyA] = rA1;
                }
                if (full || xyB < XYTOT) {
                    outk[(size_t)o0       * XYTOT + xyB] = rB0;
                    outk[(size_t)(o0 + 1) * XYTOT + xyB] = rB1;
                }
            }
        }
    }
}

extern "C" void kernel_launch(void* const* d_in, const int* in_sizes, int n_in,
                              void* d_out, int out_size)
{
    const float2* inp  = (const float2*)d_in[0];
    const float2* wgt  = (const float2*)d_in[1];
    const float2* bias = (const float2*)d_in[2];
    float2* out = (float2*)d_out;

    cudaFuncSetAttribute(cmul_k3, cudaFuncAttributeMaxDynamicSharedMemorySize, SMEM_TOTAL);

    dim3 grid(NCHUNK, KBLK);
    cmul_k3<<<grid, NTHR, SMEM_TOTAL>>>(inp, wgt, bias, out);
}

// round 10
// speedup vs baseline: 1.0201x; 1.0201x over previous
#include <cuda_runtime.h>
#include <cuda_bf16.h>
#include <cstdint>

#define KBLK   8
#define IDIM   96
#define ODIM   96
#define XYTOT  65160
#define XYH    (XYTOT/2)
#define XYT    64
#define NTHR   320
#define NCON   256
#define NTILES 1019
#define NCHUNK 18

#define PITCH      208                   // 52 words; 52%32==20 -> conflict-free, 16B-aligned
#define A_TILE     (XYT * PITCH)         // 13312
#define ABUF       (4 * A_TILE)          // 53248
#define W_TILE     (ODIM * PITCH)        // 19968
#define SM_A       1024
#define SM_W       (SM_A + 2 * ABUF)     // 107520
#define SMEM_TOTAL (SM_W + 6 * W_TILE)   // 227328

static __device__ __forceinline__ void split2(float a, float b, uint32_t& hi, uint32_t& lo) {
    uint32_t ua = __float_as_uint(a), ub = __float_as_uint(b);
    asm("prmt.b32 %0, %1, %2, 0x7632;" : "=r"(hi) : "r"(ua), "r"(ub));
    float ra = a - __uint_as_float(ua & 0xFFFF0000u);
    float rb = b - __uint_as_float(ub & 0xFFFF0000u);
    asm("cvt.rn.bf16x2.f32 %0, %1, %2;" : "=r"(lo) : "f"(rb), "f"(ra));
}
static __device__ __forceinline__ int kword(int j) {
    return ((j >> 3) << 3) + ((j & 3) << 1) + ((j >> 2) & 1);
}
static __device__ __forceinline__ uint32_t smem_u32(const void* p) {
    uint32_t a;
    asm("{ .reg .u64 t; cvta.to.shared.u64 t, %1; cvt.u32.u64 %0, t; }" : "=r"(a) : "l"(p));
    return a;
}
static __device__ __forceinline__ void mbar_wait(uint32_t addr, int parity) {
    asm volatile(
        "{ .reg .pred P;\n\t"
        "WL%=: mbarrier.try_wait.parity.acquire.cta.shared::cta.b64 P, [%0], %1, 0x989680;\n\t"
        "@P bra WD%=;\n\t"
        "bra WL%=;\n\t"
        "WD%=: }"
        :: "r"(addr), "r"((uint32_t)parity) : "memory");
}
static __device__ __forceinline__ void mbar_arrive(uint32_t addr) {
    asm volatile("mbarrier.arrive.shared.b64 _, [%0];" :: "r"(addr) : "memory");
}

#define MMA(c, a, b)                                                            \
    asm volatile("mma.sync.aligned.m16n8k16.row.col.f32.bf16.bf16.f32 "         \
        "{%0,%1,%2,%3},{%4,%5,%6,%7},{%8,%9},{%0,%1,%2,%3};"                    \
        : "+f"((c)[0]), "+f"((c)[1]), "+f"((c)[2]), "+f"((c)[3])                \
        : "r"((a)[0]), "r"((a)[1]), "r"((a)[2]), "r"((a)[3]),                   \
          "r"((b).x), "r"((b).y))

// exact compensated As = Ar + Ai split into bf16x2 (sH, sL) from stored h/l frags
static __device__ __forceinline__ void build_as(uint32_t rh, uint32_t ih,
                                                uint32_t rl, uint32_t il,
                                                uint32_t& sH, uint32_t& sL) {
    float rh0 = __uint_as_float(rh << 16), rh1 = __uint_as_float(rh & 0xFFFF0000u);
    float ih0 = __uint_as_float(ih << 16), ih1 = __uint_as_float(ih & 0xFFFF0000u);
    float sh0 = rh0 + ih0, sh1 = rh1 + ih1;
    uint32_t t0 = __float_as_uint(sh0) & 0xFFFF0000u;
    uint32_t t1 = __float_as_uint(sh1) & 0xFFFF0000u;
    asm("prmt.b32 %0, %1, %2, 0x7632;" : "=r"(sH) : "r"(t0), "r"(t1));
    float d0 = sh0 - __uint_as_float(t0);
    float d1 = sh1 - __uint_as_float(t1);
    float rl0 = __uint_as_float(rl << 16), rl1 = __uint_as_float(rl & 0xFFFF0000u);
    float il0 = __uint_as_float(il << 16), il1 = __uint_as_float(il & 0xFFFF0000u);
    float a0 = d0 + (rl0 + il0);
    float a1 = d1 + (rl1 + il1);
    asm("cvt.rn.bf16x2.f32 %0, %1, %2;" : "=r"(sL) : "f"(a1), "f"(a0));
}

// unit u (0..383): p = u/12 (xy-pair 0..31), h = u%12 -> b = h>>1 (16-i block), f = h&1
static __device__ __forceinline__ void prod_load(float4* v, const float4* s4, int u, int xy0) {
    const int p = u / 12, h = u % 12, b = h >> 1, f = h & 1;
    const int i0 = b * 16 + f * 4;
    const bool ok = (xy0 + 2 * p) < XYTOT;
    const size_t g4 = (size_t)(xy0 >> 1) + p;
    #pragma unroll
    for (int q = 0; q < 4; ++q) {
        v[q]     = ok ? __ldg(&s4[(size_t)(i0 + q)     * XYH + g4]) : make_float4(0.f,0.f,0.f,0.f);
        v[4 + q] = ok ? __ldg(&s4[(size_t)(i0 + 8 + q) * XYH + g4]) : make_float4(0.f,0.f,0.f,0.f);
    }
}
static __device__ __forceinline__ void prod_store(unsigned char* sm, const float4* v,
                                                  int u, uint32_t abase) {
    const int p = u / 12, h = u % 12, b = h >> 1, f = h & 1;
    const uint32_t chunk = (uint32_t)(b * 32 + f * 16);
    uint4 RH, RL, IH, IL;
    split2(v[0].x, v[1].x, RH.x, RL.x);  split2(v[4].x, v[5].x, RH.y, RL.y);
    split2(v[2].x, v[3].x, RH.z, RL.z);  split2(v[6].x, v[7].x, RH.w, RL.w);
    split2(v[0].y, v[1].y, IH.x, IL.x);  split2(v[4].y, v[5].y, IH.y, IL.y);
    split2(v[2].y, v[3].y, IH.z, IL.z);  split2(v[6].y, v[7].y, IH.w, IL.w);
    uint32_t off = abase + (uint32_t)(2 * p) * PITCH + chunk;
    *(uint4*)(sm + off + 0 * A_TILE) = RH;
    *(uint4*)(sm + off + 1 * A_TILE) = RL;
    *(uint4*)(sm + off + 2 * A_TILE) = IH;
    *(uint4*)(sm + off + 3 * A_TILE) = IL;
    split2(v[0].z, v[1].z, RH.x, RL.x);  split2(v[4].z, v[5].z, RH.y, RL.y);
    split2(v[2].z, v[3].z, RH.z, RL.z);  split2(v[6].z, v[7].z, RH.w, RL.w);
    split2(v[0].w, v[1].w, IH.x, IL.x);  split2(v[4].w, v[5].w, IH.y, IL.y);
    split2(v[2].w, v[3].w, IH.z, IL.z);  split2(v[6].w, v[7].w, IH.w, IL.w);
    off += PITCH;
    *(uint4*)(sm + off + 0 * A_TILE) = RH;
    *(uint4*)(sm + off + 1 * A_TILE) = RL;
    *(uint4*)(sm + off + 2 * A_TILE) = IH;
    *(uint4*)(sm + off + 3 * A_TILE) = IL;
}

__global__ __launch_bounds__(NTHR, 1)
void cmul_g3(const float2* __restrict__ inp, const float2* __restrict__ wgt,
             const float2* __restrict__ bias, float2* __restrict__ out)
{
    extern __shared__ unsigned char sm[];
    const uint32_t smb = smem_u32(sm);
    const int tid = threadIdx.x, lane = tid & 31, wid = tid >> 5;
    const int kk = blockIdx.y, chunk = blockIdx.x;

    const int basecnt = NTILES / NCHUNK;
    const int rem     = NTILES - basecnt * NCHUNK;
    const int cnt     = basecnt + (chunk < rem ? 1 : 0);
    const int t0      = chunk * basecnt + (chunk < rem ? chunk : rem);

    if (tid == 0) {
        asm volatile("mbarrier.init.shared.b64 [%0], %1;" :: "r"(smb + 0),  "r"(64u)  : "memory");
        asm volatile("mbarrier.init.shared.b64 [%0], %1;" :: "r"(smb + 8),  "r"(64u)  : "memory");
        asm volatile("mbarrier.init.shared.b64 [%0], %1;" :: "r"(smb + 16), "r"(256u) : "memory");
        asm volatile("mbarrier.init.shared.b64 [%0], %1;" :: "r"(smb + 24), "r"(256u) : "memory");
    }

    // ---- stage W variants once: [WrH, WdH, WsH, WrL, WdL, WsL], Wd=Wi-Wr, Ws=Wr+Wi ----
    for (int u = tid; u < 96 * 48; u += NTHR) {
        const int o = u / 48, j = u % 48;
        const float2* src = wgt + (size_t)kk * IDIM * ODIM + o;
        float2 wa = src[(size_t)(2 * j)     * ODIM];
        float2 wb = src[(size_t)(2 * j + 1) * ODIM];
        const uint32_t off = (uint32_t)(o * PITCH + kword(j) * 4);
        uint32_t h, l;
        split2(wa.x, wb.x, h, l);                      // Wr
        *(uint32_t*)(sm + SM_W + 0*W_TILE + off) = h;
        *(uint32_t*)(sm + SM_W + 3*W_TILE + off) = l;
        split2(wa.y - wa.x, wb.y - wb.x, h, l);        // Wd
        *(uint32_t*)(sm + SM_W + 1*W_TILE + off) = h;
        *(uint32_t*)(sm + SM_W + 4*W_TILE + off) = l;
        split2(wa.x + wa.y, wb.x + wb.y, h, l);        // Ws
        *(uint32_t*)(sm + SM_W + 2*W_TILE + off) = h;
        *(uint32_t*)(sm + SM_W + 5*W_TILE + off) = l;
    }
    __syncthreads();

    if (tid >= NCON) {
        // ================= PRODUCER (warps 8,9; 64 threads) =================
        const int ptid = tid - NCON;
        const float4* s4 = (const float4*)(inp + (size_t)kk * IDIM * XYTOT);
        int phe0 = 1, phe1 = 1;
        float4 v0[8], v1[8];
        #pragma unroll 1
        for (int t = 0; t < cnt; ++t) {
            const int buf = t & 1;
            const int xy0 = (t0 + t) * XYT;
            const uint32_t abase = SM_A + buf * ABUF;
            prod_load(v0, s4, ptid,      xy0);
            prod_load(v1, s4, ptid + 64, xy0);
            if (buf == 0) { mbar_wait(smb + 16, phe0); phe0 ^= 1; }
            else          { mbar_wait(smb + 24, phe1); phe1 ^= 1; }
            prod_store(sm, v0, ptid,       abase); prod_load(v0, s4, ptid + 128, xy0);
            prod_store(sm, v1, ptid + 64,  abase); prod_load(v1, s4, ptid + 192, xy0);
            prod_store(sm, v0, ptid + 128, abase); prod_load(v0, s4, ptid + 256, xy0);
            prod_store(sm, v1, ptid + 192, abase); prod_load(v1, s4, ptid + 320, xy0);
            prod_store(sm, v0, ptid + 256, abase);
            prod_store(sm, v1, ptid + 320, abase);
            mbar_arrive(smb + buf * 8);  // full[buf]
        }
    } else {
        // ================= CONSUMER (warps 0-7; 256 threads) =================
        const int g = lane >> 2, tig = lane & 3;
        const int warpM = (wid & 1) * 32;
        const int warpN = (wid >> 1) * 24;

        float2 bv0[3], bv1[3];
        #pragma unroll
        for (int nt = 0; nt < 3; ++nt) {
            const int o0 = warpN + nt * 8 + 2 * tig;
            bv0[nt] = bias[kk * ODIM + o0];
            bv1[nt] = bias[kk * ODIM + o0 + 1];
        }
        float2* outk = out + (size_t)kk * ODIM * XYTOT;
        const uint32_t wOff = (uint32_t)(warpN + g) * PITCH;

        int phf0 = 0, phf1 = 0;
        #pragma unroll 1
        for (int t = 0; t < cnt; ++t) {
            const int buf = t & 1;
            if (buf == 0) { mbar_wait(smb + 0, phf0); phf0 ^= 1; }
            else          { mbar_wait(smb + 8, phf1); phf1 ^= 1; }

            float acc[3][2][3][4];     // [m1,m2,m3][mt][nt][quad]
            #pragma unroll
            for (int p = 0; p < 3; ++p)
                #pragma unroll
                for (int mt = 0; mt < 2; ++mt)
                    #pragma unroll
                    for (int nt = 0; nt < 3; ++nt)
                        #pragma unroll
                        for (int q = 0; q < 4; ++q) acc[p][mt][nt][q] = 0.f;

            const uint32_t aBase = SM_A + buf * ABUF + (uint32_t)((warpM + g) * PITCH);

            #pragma unroll 1
            for (int ks = 0; ks < 6; ++ks) {
                const uint32_t koff = (uint32_t)(ks * 32 + tig * 8);
                // AF layout: 0=AsH 1=ArH 2=AiH 3=AsL 4=ArL 5=AiL
                uint32_t AF[6][2][4];
                #pragma unroll
                for (int at = 0; at < 4; ++at)          // stored: ArH,ArL,AiH,AiL
                    #pragma unroll
                    for (int mt = 0; mt < 2; ++mt) {
                        const uint32_t ad = aBase + at * A_TILE + mt * (16 * PITCH) + koff;
                        uint2 lo = *(const uint2*)(sm + ad);
                        uint2 hi = *(const uint2*)(sm + ad + 8 * PITCH);
                        const int d = (at == 0) ? 1 : (at == 1) ? 4 : (at == 2) ? 2 : 5;
                        AF[d][mt][0] = lo.x; AF[d][mt][1] = hi.x;
                        AF[d][mt][2] = lo.y; AF[d][mt][3] = hi.y;
                    }
                #pragma unroll
                for (int mt = 0; mt < 2; ++mt)
                    #pragma unroll
                    for (int r = 0; r < 4; ++r)
                        build_as(AF[1][mt][r], AF[2][mt][r], AF[4][mt][r], AF[5][mt][r],
                                 AF[0][mt][r], AF[3][mt][r]);

                uint2 Bf[6][3];
                #pragma unroll
                for (int wt = 0; wt < 6; ++wt)
                    #pragma unroll
                    for (int nt = 0; nt < 3; ++nt)
                        Bf[wt][nt] = *(const uint2*)(sm + SM_W + wt * W_TILE +
                                      wOff + (uint32_t)(nt * 8 * PITCH) + koff);

                // 9 passes: s=0 HH, s=1 A-lo x W-hi, s=2 A-hi x W-lo
                #pragma unroll
                for (int s = 0; s < 3; ++s)
                    #pragma unroll
                    for (int p = 0; p < 3; ++p) {
                        const int at = (s == 1) ? 3 + p : p;   // AF index
                        const int wt = (s == 2) ? 3 + p : p;   // W tile index
                        #pragma unroll
                        for (int nt = 0; nt < 3; ++nt)
                            #pragma unroll
                            for (int mt = 0; mt < 2; ++mt)
                                MMA(acc[p][mt][nt], AF[at][mt], Bf[wt][nt]);
                    }
            }

            mbar_arrive(smb + 16 + buf * 8);  // empty[buf]

            // epilogue: re = m1 - m3 + br ; im = m1 + m2 + bi
            const int xyb = (t0 + t) * XYT + warpM;
            const bool full = ((t0 + t) * XYT + XYT) <= XYTOT;
            #pragma unroll
            for (int nt = 0; nt < 3; ++nt) {
                const int o0 = warpN + nt * 8 + 2 * tig;
                #pragma unroll
                for (int mt = 0; mt < 2; ++mt) {
                    const int xyA = xyb + mt * 16 + g;
                    const int xyB = xyA + 8;
                    float2 rA0 = make_float2(acc[0][mt][nt][0] - acc[2][mt][nt][0] + bv0[nt].x,
                                             acc[0][mt][nt][0] + acc[1][mt][nt][0] + bv0[nt].y);
                    float2 rA1 = make_float2(acc[0][mt][nt][1] - acc[2][mt][nt][1] + bv1[nt].x,
                                             acc[0][mt][nt][1] + acc[1][mt][nt][1] + bv1[nt].y);
                    float2 rB0 = make_float2(acc[0][mt][nt][2] - acc[2][mt][nt][2] + bv0[nt].x,
                                             acc[0][mt][nt][2] + acc[1][mt][nt][2] + bv0[nt].y);
                    float2 rB1 = make_float2(acc[0][mt][nt][3] - acc[2][mt][nt][3] + bv1[nt].x,
                                             acc[0][mt][nt][3] + acc[1][mt][nt][3] + bv1[nt].y);
                    if (full || xyA < XYTOT) {
                        outk[(size_t)o0       * XYTOT + xyA] = rA0;
                        outk[(size_t)(o0 + 1) * XYTOT + xyA] = rA1;
                    }
                    if (full || xyB < XYTOT) {
                        outk[(size_t)o0       * XYTOT + xyB] = rB0;
                        outk[(size_t)(o0 + 1) * XYTOT + xyB] = rB1;
                    }
                }
            }
        }
    }
}

extern "C" void kernel_launch(void* const* d_in, const int* in_sizes, int n_in,
                              void* d_out, int out_size)
{
    const float2* inp  = (const float2*)d_in[0];
    const float2* wgt  = (const float2*)d_in[1];
    const float2* bias = (const float2*)d_in[2];
    float2* out = (float2*)d_out;

    cudaFuncSetAttribute(cmul_g3, cudaFuncAttributeMaxDynamicSharedMemorySize, SMEM_TOTAL);

    dim3 grid(NCHUNK, KBLK);
    cmul_g3<<<grid, NTHR, SMEM_TOTAL>>>(inp, wgt, bias, out);
}

// round 12
// speedup vs baseline: 1.1740x; 1.1509x over previous
#include <cuda_runtime.h>
#include <cuda_bf16.h>
#include <cstdint>

#define KBLK   8
#define IDIM   96
#define ODIM   96
#define XYTOT  65160
#define XYH    (XYTOT/2)
#define XYT    64
#define NTHR   448
#define NCON   384
#define NTILES 1019
#define NCHUNK 18

#define PITCH      224
#define A_TILE     (XYT * PITCH)         // 14336
#define ABUF       (4 * A_TILE)          // 57344
#define W_TILE     (ODIM * PITCH)        // 21504
#define SM_A       1024
#define SM_W       (SM_A + 2 * ABUF)     // 115712
#define SMEM_TOTAL (SM_W + 4 * W_TILE)   // 201728

static __device__ __forceinline__ void split2(float a, float b, uint32_t& hi, uint32_t& lo) {
    uint32_t ua = __float_as_uint(a), ub = __float_as_uint(b);
    asm("prmt.b32 %0, %1, %2, 0x7632;" : "=r"(hi) : "r"(ua), "r"(ub));
    float ra = a - __uint_as_float(ua & 0xFFFF0000u);
    float rb = b - __uint_as_float(ub & 0xFFFF0000u);
    asm("cvt.rn.bf16x2.f32 %0, %1, %2;" : "=r"(lo) : "f"(rb), "f"(ra));
}
static __device__ __forceinline__ int kword(int j) {
    return ((j >> 3) << 3) + ((j & 3) << 1) + ((j >> 2) & 1);
}
static __device__ __forceinline__ uint32_t smem_u32(const void* p) {
    uint32_t a;
    asm("{ .reg .u64 t; cvta.to.shared.u64 t, %1; cvt.u32.u64 %0, t; }" : "=r"(a) : "l"(p));
    return a;
}
static __device__ __forceinline__ void mbar_wait(uint32_t addr, int parity) {
    asm volatile(
        "{ .reg .pred P;\n\t"
        "WL%=: mbarrier.try_wait.parity.acquire.cta.shared::cta.b64 P, [%0], %1, 0x989680;\n\t"
        "@P bra WD%=;\n\t"
        "bra WL%=;\n\t"
        "WD%=: }"
        :: "r"(addr), "r"((uint32_t)parity) : "memory");
}
static __device__ __forceinline__ void mbar_arrive(uint32_t addr) {
    asm volatile("mbarrier.arrive.shared.b64 _, [%0];" :: "r"(addr) : "memory");
}

#define MMA(c, a, b)                                                            \
    asm volatile("mma.sync.aligned.m16n8k16.row.col.f32.bf16.bf16.f32 "         \
        "{%0,%1,%2,%3},{%4,%5,%6,%7},{%8,%9},{%0,%1,%2,%3};"                    \
        : "+f"((c)[0]), "+f"((c)[1]), "+f"((c)[2]), "+f"((c)[3])                \
        : "r"((a)[0]), "r"((a)[1]), "r"((a)[2]), "r"((a)[3]),                   \
          "r"((b).x), "r"((b).y))

// unit u (0..383): p = u/12 (xy-pair), h = u%12 -> b = h>>1 (16-i block), f = h&1
static __device__ __forceinline__ void prod_load(float4* v, const float4* s4, int u, int xy0) {
    const int p = u / 12, h = u % 12, b = h >> 1, f = h & 1;
    const int i0 = b * 16 + f * 4;
    const bool ok = (xy0 + 2 * p) < XYTOT;
    const size_t g4 = (size_t)(xy0 >> 1) + p;
    #pragma unroll
    for (int q = 0; q < 4; ++q) {
        v[q]     = ok ? __ldg(&s4[(size_t)(i0 + q)     * XYH + g4]) : make_float4(0.f,0.f,0.f,0.f);
        v[4 + q] = ok ? __ldg(&s4[(size_t)(i0 + 8 + q) * XYH + g4]) : make_float4(0.f,0.f,0.f,0.f);
    }
}
static __device__ __forceinline__ void prod_store(unsigned char* sm, const float4* v,
                                                  int u, uint32_t abase) {
    const int p = u / 12, h = u % 12, b = h >> 1, f = h & 1;
    const uint32_t chunk = (uint32_t)(b * 32 + f * 16);
    uint4 RH, RL, IH, IL;
    split2(v[0].x, v[1].x, RH.x, RL.x);  split2(v[4].x, v[5].x, RH.y, RL.y);
    split2(v[2].x, v[3].x, RH.z, RL.z);  split2(v[6].x, v[7].x, RH.w, RL.w);
    split2(v[0].y, v[1].y, IH.x, IL.x);  split2(v[4].y, v[5].y, IH.y, IL.y);
    split2(v[2].y, v[3].y, IH.z, IL.z);  split2(v[6].y, v[7].y, IH.w, IL.w);
    uint32_t off = abase + (uint32_t)(2 * p) * PITCH + chunk;
    *(uint4*)(sm + off + 0 * A_TILE) = RH;
    *(uint4*)(sm + off + 1 * A_TILE) = RL;
    *(uint4*)(sm + off + 2 * A_TILE) = IH;
    *(uint4*)(sm + off + 3 * A_TILE) = IL;
    split2(v[0].z, v[1].z, RH.x, RL.x);  split2(v[4].z, v[5].z, RH.y, RL.y);
    split2(v[2].z, v[3].z, RH.z, RL.z);  split2(v[6].z, v[7].z, RH.w, RL.w);
    split2(v[0].w, v[1].w, IH.x, IL.x);  split2(v[4].w, v[5].w, IH.y, IL.y);
    split2(v[2].w, v[3].w, IH.z, IL.z);  split2(v[6].w, v[7].w, IH.w, IL.w);
    off += PITCH;
    *(uint4*)(sm + off + 0 * A_TILE) = RH;
    *(uint4*)(sm + off + 1 * A_TILE) = RL;
    *(uint4*)(sm + off + 2 * A_TILE) = IH;
    *(uint4*)(sm + off + 3 * A_TILE) = IL;
}

__global__ __launch_bounds__(NTHR, 1)
void cmul_w12(const float2* __restrict__ inp, const float2* __restrict__ wgt,
              const float2* __restrict__ bias, float2* __restrict__ out)
{
    extern __shared__ unsigned char sm[];
    const uint32_t smb = smem_u32(sm);
    const int tid = threadIdx.x, lane = tid & 31, wid = tid >> 5;
    const int kk = blockIdx.y, chunk = blockIdx.x;

    const int basecnt = NTILES / NCHUNK;
    const int rem     = NTILES - basecnt * NCHUNK;
    const int cnt     = basecnt + (chunk < rem ? 1 : 0);
    const int t0      = chunk * basecnt + (chunk < rem ? chunk : rem);

    if (tid == 0) {
        asm volatile("mbarrier.init.shared.b64 [%0], %1;" :: "r"(smb + 0),  "r"(64u)  : "memory");
        asm volatile("mbarrier.init.shared.b64 [%0], %1;" :: "r"(smb + 8),  "r"(64u)  : "memory");
        asm volatile("mbarrier.init.shared.b64 [%0], %1;" :: "r"(smb + 16), "r"(384u) : "memory");
        asm volatile("mbarrier.init.shared.b64 [%0], %1;" :: "r"(smb + 24), "r"(384u) : "memory");
    }

    // ---- stage W once: Wt[o][i] -> 4 bf16 tiles ----
    for (int u = tid; u < 96 * 48; u += NTHR) {
        const int o = u / 48, j = u % 48;
        const float2* src = wgt + (size_t)kk * IDIM * ODIM + o;
        float2 wa = src[(size_t)(2 * j)     * ODIM];
        float2 wb = src[(size_t)(2 * j + 1) * ODIM];
        uint32_t rh, rl, ih, il;
        split2(wa.x, wb.x, rh, rl);
        split2(wa.y, wb.y, ih, il);
        const uint32_t off = (uint32_t)(o * PITCH + kword(j) * 4);
        *(uint32_t*)(sm + SM_W + 0 * W_TILE + off) = rh;
        *(uint32_t*)(sm + SM_W + 1 * W_TILE + off) = rl;
        *(uint32_t*)(sm + SM_W + 2 * W_TILE + off) = ih;
        *(uint32_t*)(sm + SM_W + 3 * W_TILE + off) = il;
    }
    __syncthreads();

    if (tid >= NCON) {
        // ================= PRODUCER (warps 12,13; 64 threads) =================
        const int ptid = tid - NCON;
        const float4* s4 = (const float4*)(inp + (size_t)kk * IDIM * XYTOT);
        int phe0 = 1, phe1 = 1;
        float4 v0[8], v1[8];
        #pragma unroll 1
        for (int t = 0; t < cnt; ++t) {
            const int buf = t & 1;
            const int xy0 = (t0 + t) * XYT;
            const uint32_t abase = SM_A + buf * ABUF;
            prod_load(v0, s4, ptid,      xy0);
            prod_load(v1, s4, ptid + 64, xy0);
            if (buf == 0) { mbar_wait(smb + 16, phe0); phe0 ^= 1; }
            else          { mbar_wait(smb + 24, phe1); phe1 ^= 1; }
            prod_store(sm, v0, ptid,       abase); prod_load(v0, s4, ptid + 128, xy0);
            prod_store(sm, v1, ptid + 64,  abase); prod_load(v1, s4, ptid + 192, xy0);
            prod_store(sm, v0, ptid + 128, abase); prod_load(v0, s4, ptid + 256, xy0);
            prod_store(sm, v1, ptid + 192, abase); prod_load(v1, s4, ptid + 320, xy0);
            prod_store(sm, v0, ptid + 256, abase);
            prod_store(sm, v1, ptid + 320, abase);
            mbar_arrive(smb + buf * 8);  // full[buf]
        }
    } else {
        // ================= CONSUMER (warps 0-11; 384 threads) =================
        const int g = lane >> 2, tig = lane & 3;
        const int warpM = (wid & 1) * 32;       // xy offset (2 m16 tiles)
        const int warpN = (wid >> 1) * 16;      // o offset (2 n8 tiles)

        float2 bv0[2], bv1[2];
        #pragma unroll
        for (int nt = 0; nt < 2; ++nt) {
            const int o0 = warpN + nt * 8 + 2 * tig;
            bv0[nt] = bias[kk * ODIM + o0];
            bv1[nt] = bias[kk * ODIM + o0 + 1];
        }
        float2* outk = out + (size_t)kk * ODIM * XYTOT;

        const int PA[12] = {0,1,0, 2,3,2, 2,3,2,0,1,0};
        const int PW[12] = {0,0,1, 2,2,3, 0,0,1,2,2,3};
        const int PS[12] = {0,0,0, 1,1,1, 2,2,2,2,2,2};

        int phf0 = 0, phf1 = 0;
        #pragma unroll 1
        for (int t = 0; t < cnt; ++t) {
            const int buf = t & 1;
            if (buf == 0) { mbar_wait(smb + 0, phf0); phf0 ^= 1; }
            else          { mbar_wait(smb + 8, phf1); phf1 ^= 1; }

            float acc[3][2][2][4];
            #pragma unroll
            for (int p = 0; p < 3; ++p)
                #pragma unroll
                for (int mt = 0; mt < 2; ++mt)
                    #pragma unroll
                    for (int nt = 0; nt < 2; ++nt)
                        #pragma unroll
                        for (int q = 0; q < 4; ++q) acc[p][mt][nt][q] = 0.f;

            const uint32_t aBase = SM_A + buf * ABUF + (uint32_t)((warpM + g) * PITCH);

            #pragma unroll 1
            for (int ks = 0; ks < 6; ++ks) {
                const uint32_t koff = (uint32_t)(ks * 32 + tig * 8);
                uint32_t Af[4][2][4];
                #pragma unroll
                for (int at = 0; at < 4; ++at)
                    #pragma unroll
                    for (int mt = 0; mt < 2; ++mt) {
                        const uint32_t ad = aBase + at * A_TILE + mt * (16 * PITCH) + koff;
                        uint2 lo = *(const uint2*)(sm + ad);
                        uint2 hi = *(const uint2*)(sm + ad + 8 * PITCH);
                        Af[at][mt][0] = lo.x; Af[at][mt][1] = hi.x;
                        Af[at][mt][2] = lo.y; Af[at][mt][3] = hi.y;
                    }
                uint2 Bf[4][2];
                #pragma unroll
                for (int wt = 0; wt < 4; ++wt)
                    #pragma unroll
                    for (int nt = 0; nt < 2; ++nt)
                        Bf[wt][nt] = *(const uint2*)(sm + SM_W + wt * W_TILE +
                                      (uint32_t)((warpN + nt * 8 + g) * PITCH) + koff);
                #pragma unroll
                for (int c = 0; c < 12; ++c)
                    #pragma unroll
                    for (int nt = 0; nt < 2; ++nt)
                        #pragma unroll
                        for (int mt = 0; mt < 2; ++mt)
                            MMA(acc[PS[c]][mt][nt], Af[PA[c]][mt], Bf[PW[c]][nt]);
            }

            mbar_arrive(smb + 16 + buf * 8);  // empty[buf] (acc in regs)

            const int xyb = (t0 + t) * XYT + warpM;
            const bool full = ((t0 + t) * XYT + XYT) <= XYTOT;
            #pragma unroll
            for (int nt = 0; nt < 2; ++nt) {
                const int o0 = warpN + nt * 8 + 2 * tig;
                #pragma unroll
                for (int mt = 0; mt < 2; ++mt) {
                    const int xyA = xyb + mt * 16 + g;
                    const int xyB = xyA + 8;
                    if (full || xyA < XYTOT) {
                        outk[(size_t)o0 * XYTOT + xyA] = make_float2(
                            acc[0][mt][nt][0] - acc[1][mt][nt][0] + bv0[nt].x,
                            acc[2][mt][nt][0] + bv0[nt].y);
                        outk[(size_t)(o0 + 1) * XYTOT + xyA] = make_float2(
                            acc[0][mt][nt][1] - acc[1][mt][nt][1] + bv1[nt].x,
                            acc[2][mt][nt][1] + bv1[nt].y);
                    }
                    if (full || xyB < XYTOT) {
                        outk[(size_t)o0 * XYTOT + xyB] = make_float2(
                            acc[0][mt][nt][2] - acc[1][mt][nt][2] + bv0[nt].x,
                            acc[2][mt][nt][2] + bv0[nt].y);
                        outk[(size_t)(o0 + 1) * XYTOT + xyB] = make_float2(
                            acc[0][mt][nt][3] - acc[1][mt][nt][3] + bv1[nt].x,
                            acc[2][mt][nt][3] + bv1[nt].y);
                    }
                }
            }
        }
    }
}

extern "C" void kernel_launch(void* const* d_in, const int* in_sizes, int n_in,
                              void* d_out, int out_size)
{
    const float2* inp  = (const float2*)d_in[0];
    const float2* wgt  = (const float2*)d_in[1];
    const float2* bias = (const float2*)d_in[2];
    float2* out = (float2*)d_out;

    cudaFuncSetAttribute(cmul_w12, cudaFuncAttributeMaxDynamicSharedMemorySize, SMEM_TOTAL);

    dim3 grid(NCHUNK, KBLK);
    cmul_w12<<<grid, NTHR, SMEM_TOTAL>>>(inp, wgt, bias, out);
}